// round 5
// baseline (speedup 1.0000x reference)
#include <cuda_runtime.h>
#include <cuda_bf16.h>
#include <cstdint>

#define NN 50000
#define EE 800000
#define DD 128
#define LL 3
#define NB 196                        // scan blocks: ceil(50000/256)

// ---------------- device scratch ----------------
__device__ float g_buf0[NN * DD];
__device__ float g_buf1[NN * DD];
__device__ int   g_rowptr[NN + 1];
__device__ int   g_counts[NN];
__device__ int   g_bsum[NB];
__device__ int   g_srcs  [EE];
__device__ int   g_src_in[EE];
__device__ int   g_dst_in[EE];
__device__ int   g_is32;
// transposed bf16 weights: [layer][n=128][k=256] (k<128 -> Wrel, else Wroot)
__device__ unsigned short g_Bth[LL * DD * 2 * DD];
__device__ unsigned short g_Btl[LL * DD * 2 * DD];

// ---------------- CSR build ----------------
__global__ void zero_counts_kernel() {
    int i = blockIdx.x * blockDim.x + threadIdx.x;
    if (i < NN) g_counts[i] = 0;
    if (i == 0) g_is32 = 0;
}

// Sample first 16384 odd 32-bit words. int64 edges -> all high halves zero.
__global__ void detect_kernel(const unsigned int* __restrict__ w) {
    int i = blockIdx.x * blockDim.x + threadIdx.x;   // 0..4095
    unsigned int acc = 0;
    #pragma unroll
    for (int j = 0; j < 4; j++) acc |= w[2 * (i * 4 + j) + 1];
    if (acc) g_is32 = 1;
}

__global__ void convert_hist_kernel(const void* __restrict__ edges) {
    int e = blockIdx.x * blockDim.x + threadIdx.x;
    if (e >= EE) return;
    int s, d;
    if (g_is32) {
        const int* p = (const int*)edges;
        s = p[e]; d = p[EE + e];
    } else {
        const long long* p = (const long long*)edges;
        s = (int)p[e]; d = (int)p[EE + e];
    }
    g_src_in[e] = s;
    g_dst_in[e] = d;
    atomicAdd(&g_counts[d], 1);
}

__global__ void scan_red_kernel() {
    __shared__ int s[256];
    int b = blockIdx.x, t = threadIdx.x;
    int i = b * 256 + t;
    s[t] = (i < NN) ? g_counts[i] : 0;
    __syncthreads();
    #pragma unroll
    for (int o = 128; o > 0; o >>= 1) {
        if (t < o) s[t] += s[t + o];
        __syncthreads();
    }
    if (t == 0) g_bsum[b] = s[0];
}

__global__ void scan_mid_kernel() {
    __shared__ int s[256];
    int t = threadIdx.x;
    int v = (t < NB) ? g_bsum[t] : 0;
    s[t] = v;
    __syncthreads();
    #pragma unroll
    for (int o = 1; o < 256; o <<= 1) {
        int u = (t >= o) ? s[t - o] : 0;
        __syncthreads();
        s[t] += u;
        __syncthreads();
    }
    if (t < NB) g_bsum[t] = s[t] - v;
    if (t == 255) g_rowptr[NN] = s[255];
}

__global__ void scan_final_kernel() {
    __shared__ int s[256];
    int b = blockIdx.x, t = threadIdx.x;
    int i = b * 256 + t;
    int v = (i < NN) ? g_counts[i] : 0;
    s[t] = v;
    __syncthreads();
    #pragma unroll
    for (int o = 1; o < 256; o <<= 1) {
        int u = (t >= o) ? s[t - o] : 0;
        __syncthreads();
        s[t] += u;
        __syncthreads();
    }
    if (i < NN) {
        g_rowptr[i] = g_bsum[b] + s[t] - v;
        g_counts[i] = 0;
    }
}

__global__ void fill_kernel() {
    int e = blockIdx.x * blockDim.x + threadIdx.x;
    if (e >= EE) return;
    int d = g_dst_in[e];
    int pos = g_rowptr[d] + atomicAdd(&g_counts[d], 1);
    g_srcs[pos] = g_src_in[e];
}

// ---------------- weight prep ----------------
__global__ void wprep_kernel(const float* __restrict__ Wrel,
                             const float* __restrict__ Wroot) {
    int idx = blockIdx.x * blockDim.x + threadIdx.x;
    if (idx >= LL * 256 * DD) return;
    int l = idx / (256 * DD);
    int r = idx - l * 256 * DD;
    int k = r / DD;
    int n = r - k * DD;
    float w = (k < DD) ? Wrel[(size_t)l * DD * DD + k * DD + n]
                       : Wroot[(size_t)l * DD * DD + (k - DD) * DD + n];
    __nv_bfloat16 hi = __float2bfloat16(w);
    float lo = w - __bfloat162float(hi);
    __nv_bfloat16 lob = __float2bfloat16(lo);
    size_t o = (size_t)l * DD * 256 + (size_t)n * 256 + k;
    g_Bth[o] = *(unsigned short*)&hi;
    g_Btl[o] = *(unsigned short*)&lob;
}

// ---------------- fused agg + GEMM kernel ----------------
// Per block (BM=64 rows): phase 1 gathers+aggregates its 64 nodes (warp per
// node, edges unrolled x4) and writes bf16 hi/lo directly into the MMA A-plane
// layout for chunks 0..3. Phase 2: 8-chunk MMA loop (chunks 4..7 = x, staged
// double-buffered). 100KB smem -> 2 blocks/SM -> gather of one block overlaps
// MMA of the other.

#define BM   64
#define BK   32
#define ROWB 80
#define APL  5120                     // A plane bytes (64*80)
#define BPL  10240                    // B plane bytes (128*80)
#define AGGB 40960                    // 4 chunks * 2*APL
#define STGB 30720                    // A_HI 0, A_LO 5120, B_HI 10240, B_LO 20480
#define SA_LO APL
#define SB_HI (2*APL)
#define SB_LO (2*APL + BPL)
#define SMTOT (AGGB + 2*STGB)         // 102400

__device__ __forceinline__ void mma16816(float* c, const uint32_t* a, const uint32_t* b) {
    asm volatile(
        "mma.sync.aligned.m16n8k16.row.col.f32.bf16.bf16.f32 "
        "{%0,%1,%2,%3}, {%4,%5,%6,%7}, {%8,%9}, {%0,%1,%2,%3};"
        : "+f"(c[0]), "+f"(c[1]), "+f"(c[2]), "+f"(c[3])
        : "r"(a[0]), "r"(a[1]), "r"(a[2]), "r"(a[3]), "r"(b[0]), "r"(b[1]));
}

__device__ __forceinline__ uint32_t pack_bf2f(float a, float b) {
    __nv_bfloat16 ha = __float2bfloat16(a), hb = __float2bfloat16(b);
    uint16_t ua = *(uint16_t*)&ha, ub = *(uint16_t*)&hb;
    return (uint32_t)ua | ((uint32_t)ub << 16);
}

__global__ void __launch_bounds__(256, 2) fused_kernel(
    const float* __restrict__ xin,
    int layer,
    const float* __restrict__ bias,
    float* __restrict__ out)
{
    extern __shared__ char smem[];
    int tid  = threadIdx.x;
    int wid  = tid >> 5;
    int lane = tid & 31;
    int g    = lane >> 2;
    int t    = lane & 3;
    int row0 = blockIdx.x * BM;
    int m0w  = (wid >> 2) * 32;       // 2 warp-rows of 32
    int n0w  = (wid & 3) * 32;        // 4 warp-cols of 32

    // ---- phase 1: gather + aggregate 64 nodes, write agg planes ----
    {
        int klc = lane >> 3;          // chunk 0..3
        uint32_t off0 = 8 * (lane & 7);
        char* chunk = smem + klc * (2 * APL);
        #pragma unroll 1
        for (int i = 0; i < 8; i++) {
            int m = wid * 8 + i;
            int grow = row0 + m;
            float4 acc = make_float4(0.f, 0.f, 0.f, 0.f);
            if (grow < NN) {
                int beg = g_rowptr[grow], end = g_rowptr[grow + 1];
                const float* xb = xin + lane * 4;
                int e = beg;
                for (; e + 3 < end; e += 4) {
                    int s0 = g_srcs[e], s1 = g_srcs[e+1], s2 = g_srcs[e+2], s3 = g_srcs[e+3];
                    float4 v0 = *(const float4*)(xb + (size_t)s0 * DD);
                    float4 v1 = *(const float4*)(xb + (size_t)s1 * DD);
                    float4 v2 = *(const float4*)(xb + (size_t)s2 * DD);
                    float4 v3 = *(const float4*)(xb + (size_t)s3 * DD);
                    acc.x += (v0.x + v1.x) + (v2.x + v3.x);
                    acc.y += (v0.y + v1.y) + (v2.y + v3.y);
                    acc.z += (v0.z + v1.z) + (v2.z + v3.z);
                    acc.w += (v0.w + v1.w) + (v2.w + v3.w);
                }
                for (; e < end; e++) {
                    float4 v = *(const float4*)(xb + (size_t)g_srcs[e] * DD);
                    acc.x += v.x; acc.y += v.y; acc.z += v.z; acc.w += v.w;
                }
            }
            float lx = acc.x - __bfloat162float(__float2bfloat16(acc.x));
            float ly = acc.y - __bfloat162float(__float2bfloat16(acc.y));
            float lz = acc.z - __bfloat162float(__float2bfloat16(acc.z));
            float lw = acc.w - __bfloat162float(__float2bfloat16(acc.w));
            uint32_t off = (uint32_t)m * ROWB + off0;
            *(uint32_t*)(chunk + off)           = pack_bf2f(acc.x, acc.y);
            *(uint32_t*)(chunk + off + 4)       = pack_bf2f(acc.z, acc.w);
            *(uint32_t*)(chunk + APL + off)     = pack_bf2f(lx, ly);
            *(uint32_t*)(chunk + APL + off + 4) = pack_bf2f(lz, lw);
        }
    }

    // ---- phase 2: MMA over 8 K32 chunks (0..3 agg smem, 4..7 x staged) ----
    const uint32_t* Bth = (const uint32_t*)(g_Bth + (size_t)layer * DD * 256);
    const uint32_t* Btl = (const uint32_t*)(g_Btl + (size_t)layer * DD * 256);

    float acc[2][4][4];
    #pragma unroll
    for (int i = 0; i < 2; i++)
        #pragma unroll
        for (int j = 0; j < 4; j++)
            #pragma unroll
            for (int q = 0; q < 4; q++) acc[i][j][q] = 0.f;

    float4   av[2];
    uint32_t bhv[8], blv[8];

    auto load_regs = [&](int c) {
        if (c >= 4) {
            int kc = (c - 4) * BK;
            #pragma unroll
            for (int j = 0; j < 2; j++) {
                int p = j * 256 + tid;     // 0..511
                int m = p >> 3;
                int kq = p & 7;
                int grow = row0 + m;
                av[j] = make_float4(0.f, 0.f, 0.f, 0.f);
                if (grow < NN)
                    av[j] = *(const float4*)(xin + (size_t)grow * DD + DD * 0 + kc + 4 * kq);
            }
        }
        #pragma unroll
        for (int j = 0; j < 8; j++) {
            int p = j * 256 + tid;
            int n = p >> 4;
            int kp = p & 15;
            int ui = n * 128 + c * 16 + kp;
            bhv[j] = Bth[ui];
            blv[j] = Btl[ui];
        }
    };

    auto store_smem = [&](int c, int buf) {
        char* base = smem + AGGB + buf * STGB;
        if (c >= 4) {
            #pragma unroll
            for (int j = 0; j < 2; j++) {
                int p = j * 256 + tid;
                int m = p >> 3;
                int kq = p & 7;
                float4 v = av[j];
                float lx = v.x - __bfloat162float(__float2bfloat16(v.x));
                float ly = v.y - __bfloat162float(__float2bfloat16(v.y));
                float lz = v.z - __bfloat162float(__float2bfloat16(v.z));
                float lw = v.w - __bfloat162float(__float2bfloat16(v.w));
                uint32_t off = (uint32_t)m * ROWB + 8 * kq;
                *(uint32_t*)(base + off)             = pack_bf2f(v.x, v.y);
                *(uint32_t*)(base + off + 4)         = pack_bf2f(v.z, v.w);
                *(uint32_t*)(base + SA_LO + off)     = pack_bf2f(lx, ly);
                *(uint32_t*)(base + SA_LO + off + 4) = pack_bf2f(lz, lw);
            }
        }
        #pragma unroll
        for (int j = 0; j < 8; j++) {
            int p = j * 256 + tid;
            int n = p >> 4;
            int kp = p & 15;
            uint32_t off = (uint32_t)n * ROWB + 4 * kp;
            *(uint32_t*)(base + SB_HI + off) = bhv[j];
            *(uint32_t*)(base + SB_LO + off) = blv[j];
        }
    };

    load_regs(0);
    store_smem(0, 0);
    __syncthreads();      // covers agg planes + staging buf0

    #pragma unroll 1
    for (int c = 0; c < 8; c++) {
        if (c < 7) load_regs(c + 1);

        const char* stg = smem + AGGB + (c & 1) * STGB;
        const char* aB  = (c < 4) ? (smem + c * (2 * APL)) : stg;
        #pragma unroll
        for (int s = 0; s < 2; s++) {
            uint32_t ah[2][4], al[2][4], bh[4][2], bl[4][2];
            #pragma unroll
            for (int mt = 0; mt < 2; mt++) {
                uint32_t r0 = (uint32_t)(m0w + mt * 16 + g) * ROWB + s * 32 + 4 * t;
                uint32_t r1 = r0 + 8 * ROWB;
                ah[mt][0] = *(const uint32_t*)(aB + r0);
                ah[mt][1] = *(const uint32_t*)(aB + r1);
                ah[mt][2] = *(const uint32_t*)(aB + r0 + 16);
                ah[mt][3] = *(const uint32_t*)(aB + r1 + 16);
                al[mt][0] = *(const uint32_t*)(aB + APL + r0);
                al[mt][1] = *(const uint32_t*)(aB + APL + r1);
                al[mt][2] = *(const uint32_t*)(aB + APL + r0 + 16);
                al[mt][3] = *(const uint32_t*)(aB + APL + r1 + 16);
            }
            #pragma unroll
            for (int nt = 0; nt < 4; nt++) {
                uint32_t rb = (uint32_t)(n0w + nt * 8 + g) * ROWB + s * 32 + 4 * t;
                bh[nt][0] = *(const uint32_t*)(stg + SB_HI + rb);
                bh[nt][1] = *(const uint32_t*)(stg + SB_HI + rb + 16);
                bl[nt][0] = *(const uint32_t*)(stg + SB_LO + rb);
                bl[nt][1] = *(const uint32_t*)(stg + SB_LO + rb + 16);
            }
            #pragma unroll
            for (int mt = 0; mt < 2; mt++)
                #pragma unroll
                for (int nt = 0; nt < 4; nt++) {
                    mma16816(acc[mt][nt], ah[mt], bh[nt]);
                    mma16816(acc[mt][nt], ah[mt], bl[nt]);
                    mma16816(acc[mt][nt], al[mt], bh[nt]);
                }
        }
        if (c < 7) {
            __syncthreads();          // staging buf (c+1)&1 free (readers of it done)
            store_smem(c + 1, (c + 1) & 1);
            __syncthreads();
        }
    }

    // ---- epilogue ----
    #pragma unroll
    for (int nt = 0; nt < 4; nt++) {
        int col = n0w + nt * 8 + 2 * t;
        float b0 = bias[col], b1 = bias[col + 1];
        #pragma unroll
        for (int mt = 0; mt < 2; mt++) {
            int r = row0 + m0w + mt * 16 + g;
            if (r < NN) {
                float2 o0 = make_float2(acc[mt][nt][0] + b0, acc[mt][nt][1] + b1);
                *(float2*)(out + (size_t)r * DD + col) = o0;
            }
            if (r + 8 < NN) {
                float2 o1 = make_float2(acc[mt][nt][2] + b0, acc[mt][nt][3] + b1);
                *(float2*)(out + (size_t)(r + 8) * DD + col) = o1;
            }
        }
    }
}

// ---------------- launch ----------------
extern "C" void kernel_launch(void* const* d_in, const int* in_sizes, int n_in,
                              void* d_out, int out_size) {
    const float* x     = (const float*)d_in[0];
    const void*  edges = d_in[1];
    const float* Wrel  = (const float*)d_in[2];
    const float* Wroot = (const float*)d_in[3];
    const float* bias  = (const float*)d_in[4];
    float*       out   = (float*)d_out;

    float *buf0, *buf1;
    cudaGetSymbolAddress((void**)&buf0, g_buf0);
    cudaGetSymbolAddress((void**)&buf1, g_buf1);

    cudaFuncSetAttribute(fused_kernel,
                         cudaFuncAttributeMaxDynamicSharedMemorySize, SMTOT);

    const int T = 256;
    int gbN = (NN + T - 1) / T;
    int gbE = (EE + T - 1) / T;

    zero_counts_kernel<<<gbN, T>>>();
    detect_kernel<<<16, 256>>>((const unsigned int*)edges);
    convert_hist_kernel<<<gbE, T>>>(edges);
    scan_red_kernel<<<NB, 256>>>();
    scan_mid_kernel<<<1, 256>>>();
    scan_final_kernel<<<NB, 256>>>();
    fill_kernel<<<gbE, T>>>();
    wprep_kernel<<<(LL * 256 * DD + T - 1) / T, T>>>(Wrel, Wroot);

    int blocks = (NN + BM - 1) / BM;   // 782

    const float* cur = x;
    float* outs[LL] = { buf0, buf1, out };
    for (int l = 0; l < LL; l++) {
        fused_kernel<<<blocks, T, SMTOT>>>(cur, l, bias + (size_t)l * DD, outs[l]);
        cur = outs[l];
    }
}

// round 7
// speedup vs baseline: 1.0263x; 1.0263x over previous
#include <cuda_runtime.h>
#include <cuda_bf16.h>
#include <cstdint>

#define NN 50000
#define EE 800000
#define DD 128
#define LL 3
#define NB 196                        // scan blocks: ceil(50000/256)

// ---------------- device scratch ----------------
__device__ float g_buf0[NN * DD];
__device__ float g_buf1[NN * DD];
__device__ float g_agg [NN * DD];
__device__ int   g_rowptr[NN + 1];
__device__ int   g_counts[NN];
__device__ int   g_bsum[NB];
__device__ int   g_srcs  [EE];
__device__ int   g_src_in[EE];
__device__ int   g_dst_in[EE];
__device__ int   g_is32;
// transposed bf16 weights: [layer][n=128][k=256] (k<128 -> Wrel, else Wroot)
__device__ unsigned short g_Bth[LL * DD * 2 * DD];
__device__ unsigned short g_Btl[LL * DD * 2 * DD];

// ---------------- CSR build ----------------
__global__ void zero_counts_kernel() {
    int i = blockIdx.x * blockDim.x + threadIdx.x;
    if (i < NN) g_counts[i] = 0;
    if (i == 0) g_is32 = 0;
}

// Sample first 16384 odd 32-bit words. int64 edges -> all high halves zero.
__global__ void detect_kernel(const unsigned int* __restrict__ w) {
    int i = blockIdx.x * blockDim.x + threadIdx.x;   // 0..4095
    unsigned int acc = 0;
    #pragma unroll
    for (int j = 0; j < 4; j++) acc |= w[2 * (i * 4 + j) + 1];
    if (acc) g_is32 = 1;
}

__global__ void convert_hist_kernel(const void* __restrict__ edges) {
    int e = blockIdx.x * blockDim.x + threadIdx.x;
    if (e >= EE) return;
    int s, d;
    if (g_is32) {
        const int* p = (const int*)edges;
        s = p[e]; d = p[EE + e];
    } else {
        const long long* p = (const long long*)edges;
        s = (int)p[e]; d = (int)p[EE + e];
    }
    g_src_in[e] = s;
    g_dst_in[e] = d;
    atomicAdd(&g_counts[d], 1);
}

__global__ void scan_red_kernel() {
    __shared__ int s[256];
    int b = blockIdx.x, t = threadIdx.x;
    int i = b * 256 + t;
    s[t] = (i < NN) ? g_counts[i] : 0;
    __syncthreads();
    #pragma unroll
    for (int o = 128; o > 0; o >>= 1) {
        if (t < o) s[t] += s[t + o];
        __syncthreads();
    }
    if (t == 0) g_bsum[b] = s[0];
}

__global__ void scan_mid_kernel() {
    __shared__ int s[256];
    int t = threadIdx.x;
    int v = (t < NB) ? g_bsum[t] : 0;
    s[t] = v;
    __syncthreads();
    #pragma unroll
    for (int o = 1; o < 256; o <<= 1) {
        int u = (t >= o) ? s[t - o] : 0;
        __syncthreads();
        s[t] += u;
        __syncthreads();
    }
    if (t < NB) g_bsum[t] = s[t] - v;
    if (t == 255) g_rowptr[NN] = s[255];
}

__global__ void scan_final_kernel() {
    __shared__ int s[256];
    int b = blockIdx.x, t = threadIdx.x;
    int i = b * 256 + t;
    int v = (i < NN) ? g_counts[i] : 0;
    s[t] = v;
    __syncthreads();
    #pragma unroll
    for (int o = 1; o < 256; o <<= 1) {
        int u = (t >= o) ? s[t - o] : 0;
        __syncthreads();
        s[t] += u;
        __syncthreads();
    }
    if (i < NN) {
        g_rowptr[i] = g_bsum[b] + s[t] - v;
        g_counts[i] = 0;
    }
}

__global__ void fill_kernel() {
    int e = blockIdx.x * blockDim.x + threadIdx.x;
    if (e >= EE) return;
    int d = g_dst_in[e];
    int pos = g_rowptr[d] + atomicAdd(&g_counts[d], 1);
    g_srcs[pos] = g_src_in[e];
}

// ---------------- weight prep ----------------
__global__ void wprep_kernel(const float* __restrict__ Wrel,
                             const float* __restrict__ Wroot) {
    int idx = blockIdx.x * blockDim.x + threadIdx.x;
    if (idx >= LL * 256 * DD) return;
    int l = idx / (256 * DD);
    int r = idx - l * 256 * DD;
    int k = r / DD;
    int n = r - k * DD;
    float w = (k < DD) ? Wrel[(size_t)l * DD * DD + k * DD + n]
                       : Wroot[(size_t)l * DD * DD + (k - DD) * DD + n];
    __nv_bfloat16 hi = __float2bfloat16(w);
    float lo = w - __bfloat162float(hi);
    __nv_bfloat16 lob = __float2bfloat16(lo);
    size_t o = (size_t)l * DD * 256 + (size_t)n * 256 + k;
    g_Bth[o] = *(unsigned short*)&hi;
    g_Btl[o] = *(unsigned short*)&lob;
}

// ---------------- aggregation: one warp per destination node ----------------
__global__ void agg_kernel(const float* __restrict__ x) {
    int gw   = (blockIdx.x * blockDim.x + threadIdx.x) >> 5;
    int lane = threadIdx.x & 31;
    if (gw >= NN) return;
    int beg = g_rowptr[gw], end = g_rowptr[gw + 1];
    float4 acc = make_float4(0.f, 0.f, 0.f, 0.f);
    const float* xb = x + lane * 4;
    for (int e = beg; e < end; e++) {
        int s = g_srcs[e];
        float4 v = *(const float4*)(xb + (size_t)s * DD);
        acc.x += v.x; acc.y += v.y; acc.z += v.z; acc.w += v.w;
    }
    *(float4*)(g_agg + (size_t)gw * DD + lane * 4) = acc;
}

// ---------------- half-K tensor-core GEMM (K=128, HMMA) ----------------------
// out[m][n] (+)= sum_k A[m][k] W[k][n] (+ bias[n] if !accum)
// koff32: 0 -> Wrel half, 64 -> Wroot half (uint32 units into [n][256] weights)

#define BK 32
#define ROWB 80
#define BUFB 40960                    // 4 planes * 128 rows * 80B
#define OFF_AH 0
#define OFF_AL 10240
#define OFF_BH 20480
#define OFF_BL 30720

__device__ __forceinline__ void mma16816(float* c, const uint32_t* a, const uint32_t* b) {
    asm volatile(
        "mma.sync.aligned.m16n8k16.row.col.f32.bf16.bf16.f32 "
        "{%0,%1,%2,%3}, {%4,%5,%6,%7}, {%8,%9}, {%0,%1,%2,%3};"
        : "+f"(c[0]), "+f"(c[1]), "+f"(c[2]), "+f"(c[3])
        : "r"(a[0]), "r"(a[1]), "r"(a[2]), "r"(a[3]), "r"(b[0]), "r"(b[1]));
}

__device__ __forceinline__ uint32_t pack_bf2f(float a, float b) {
    __nv_bfloat16 ha = __float2bfloat16(a), hb = __float2bfloat16(b);
    uint16_t ua = *(uint16_t*)&ha, ub = *(uint16_t*)&hb;
    return (uint32_t)ua | ((uint32_t)ub << 16);
}

__global__ void __launch_bounds__(256) gemm_half_kernel(
    const float* __restrict__ Asrc,
    int layer, int koff32,
    const float* __restrict__ bias,
    float* __restrict__ out, int accum)
{
    extern __shared__ char smem[];
    int tid  = threadIdx.x;
    int wid  = tid >> 5;
    int lane = tid & 31;
    int g    = lane >> 2;
    int t    = lane & 3;
    int row0 = blockIdx.x * 128;
    int m0w  = (wid >> 2) * 64;
    int n0w  = (wid & 3) * 32;

    const uint32_t* Bth = (const uint32_t*)(g_Bth + (size_t)layer * DD * 256) + koff32;
    const uint32_t* Btl = (const uint32_t*)(g_Btl + (size_t)layer * DD * 256) + koff32;

    float acc[4][4][4];
    #pragma unroll
    for (int i = 0; i < 4; i++)
        #pragma unroll
        for (int j = 0; j < 4; j++)
            #pragma unroll
            for (int q = 0; q < 4; q++) acc[i][j][q] = 0.f;

    float4   av[4];
    uint32_t bhv[8], blv[8];

    auto load_regs = [&](int c) {
        int kc = c * BK;
        #pragma unroll
        for (int j = 0; j < 4; j++) {
            int p = j * 256 + tid;
            int m = p >> 3;
            int kq = p & 7;
            int grow = row0 + m;
            av[j] = make_float4(0.f, 0.f, 0.f, 0.f);
            if (grow < NN)
                av[j] = *(const float4*)(Asrc + (size_t)grow * DD + kc + 4 * kq);
        }
        #pragma unroll
        for (int j = 0; j < 8; j++) {
            int p = j * 256 + tid;
            int n = p >> 4;
            int kp = p & 15;
            int ui = n * 128 + c * 16 + kp;
            bhv[j] = Bth[ui];
            blv[j] = Btl[ui];
        }
    };

    auto store_smem = [&](int buf) {
        char* base = smem + buf * BUFB;
        #pragma unroll
        for (int j = 0; j < 4; j++) {
            int p = j * 256 + tid;
            int m = p >> 3;
            int kq = p & 7;
            float4 v = av[j];
            float lx = v.x - __bfloat162float(__float2bfloat16(v.x));
            float ly = v.y - __bfloat162float(__float2bfloat16(v.y));
            float lz = v.z - __bfloat162float(__float2bfloat16(v.z));
            float lw = v.w - __bfloat162float(__float2bfloat16(v.w));
            uint32_t off = (uint32_t)m * ROWB + 8 * kq;
            *(uint32_t*)(base + OFF_AH + off)     = pack_bf2f(v.x, v.y);
            *(uint32_t*)(base + OFF_AH + off + 4) = pack_bf2f(v.z, v.w);
            *(uint32_t*)(base + OFF_AL + off)     = pack_bf2f(lx, ly);
            *(uint32_t*)(base + OFF_AL + off + 4) = pack_bf2f(lz, lw);
        }
        #pragma unroll
        for (int j = 0; j < 8; j++) {
            int p = j * 256 + tid;
            int n = p >> 4;
            int kp = p & 15;
            uint32_t off = (uint32_t)n * ROWB + 4 * kp;
            *(uint32_t*)(base + OFF_BH + off) = bhv[j];
            *(uint32_t*)(base + OFF_BL + off) = blv[j];
        }
    };

    load_regs(0);
    store_smem(0);
    __syncthreads();

    #pragma unroll 1
    for (int c = 0; c < 4; c++) {
        if (c < 3) load_regs(c + 1);

        const char* base = smem + (c & 1) * BUFB;
        #pragma unroll
        for (int s = 0; s < 2; s++) {
            uint32_t ah[4][4], al[4][4], bh[4][2], bl[4][2];
            #pragma unroll
            for (int mt = 0; mt < 4; mt++) {
                uint32_t r0 = (uint32_t)(m0w + mt * 16 + g) * ROWB + s * 32 + 4 * t;
                uint32_t r1 = r0 + 8 * ROWB;
                ah[mt][0] = *(const uint32_t*)(base + OFF_AH + r0);
                ah[mt][1] = *(const uint32_t*)(base + OFF_AH + r1);
                ah[mt][2] = *(const uint32_t*)(base + OFF_AH + r0 + 16);
                ah[mt][3] = *(const uint32_t*)(base + OFF_AH + r1 + 16);
                al[mt][0] = *(const uint32_t*)(base + OFF_AL + r0);
                al[mt][1] = *(const uint32_t*)(base + OFF_AL + r1);
                al[mt][2] = *(const uint32_t*)(base + OFF_AL + r0 + 16);
                al[mt][3] = *(const uint32_t*)(base + OFF_AL + r1 + 16);
            }
            #pragma unroll
            for (int nt = 0; nt < 4; nt++) {
                uint32_t rb = (uint32_t)(n0w + nt * 8 + g) * ROWB + s * 32 + 4 * t;
                bh[nt][0] = *(const uint32_t*)(base + OFF_BH + rb);
                bh[nt][1] = *(const uint32_t*)(base + OFF_BH + rb + 16);
                bl[nt][0] = *(const uint32_t*)(base + OFF_BL + rb);
                bl[nt][1] = *(const uint32_t*)(base + OFF_BL + rb + 16);
            }
            #pragma unroll
            for (int mt = 0; mt < 4; mt++)
                #pragma unroll
                for (int nt = 0; nt < 4; nt++) {
                    mma16816(acc[mt][nt], ah[mt], bh[nt]);
                    mma16816(acc[mt][nt], ah[mt], bl[nt]);
                    mma16816(acc[mt][nt], al[mt], bh[nt]);
                }
        }
        if (c < 3) {
            store_smem((c + 1) & 1);
            __syncthreads();
        }
    }

    #pragma unroll
    for (int nt = 0; nt < 4; nt++) {
        int col = n0w + nt * 8 + 2 * t;
        float b0 = 0.f, b1 = 0.f;
        if (!accum) { b0 = bias[col]; b1 = bias[col + 1]; }
        #pragma unroll
        for (int mt = 0; mt < 4; mt++) {
            int r = row0 + m0w + mt * 16 + g;
            if (r < NN) {
                float2 o;
                if (accum) {
                    float2 p = *(const float2*)(out + (size_t)r * DD + col);
                    o = make_float2(acc[mt][nt][0] + p.x, acc[mt][nt][1] + p.y);
                } else {
                    o = make_float2(acc[mt][nt][0] + b0, acc[mt][nt][1] + b1);
                }
                *(float2*)(out + (size_t)r * DD + col) = o;
            }
            if (r + 8 < NN) {
                float2 o;
                if (accum) {
                    float2 p = *(const float2*)(out + (size_t)(r + 8) * DD + col);
                    o = make_float2(acc[mt][nt][2] + p.x, acc[mt][nt][3] + p.y);
                } else {
                    o = make_float2(acc[mt][nt][2] + b0, acc[mt][nt][3] + b1);
                }
                *(float2*)(out + (size_t)(r + 8) * DD + col) = o;
            }
        }
    }
}

// ---------------- launch ----------------
extern "C" void kernel_launch(void* const* d_in, const int* in_sizes, int n_in,
                              void* d_out, int out_size) {
    const float* x     = (const float*)d_in[0];
    const void*  edges = d_in[1];
    const float* Wrel  = (const float*)d_in[2];
    const float* Wroot = (const float*)d_in[3];
    const float* bias  = (const float*)d_in[4];
    float*       out   = (float*)d_out;

    float *buf0, *buf1, *aggp;
    cudaGetSymbolAddress((void**)&buf0, g_buf0);
    cudaGetSymbolAddress((void**)&buf1, g_buf1);
    cudaGetSymbolAddress((void**)&aggp, g_agg);   // device address (host-side symbol is NOT one)

    // persistent host-side stream/events (device work per call is identical)
    struct Res {
        cudaStream_t s2;
        cudaEvent_t evA[LL], evB[LL];
        Res() {
            cudaStreamCreateWithFlags(&s2, cudaStreamNonBlocking);
            for (int i = 0; i < LL; i++) {
                cudaEventCreateWithFlags(&evA[i], cudaEventDisableTiming);
                cudaEventCreateWithFlags(&evB[i], cudaEventDisableTiming);
            }
        }
    };
    static Res R;

    cudaFuncSetAttribute(gemm_half_kernel,
                         cudaFuncAttributeMaxDynamicSharedMemorySize, 2 * BUFB);

    const int T = 256;
    int gbN = (NN + T - 1) / T;
    int gbE = (EE + T - 1) / T;
    int aggBlocks  = (NN * 32 + T - 1) / T;
    int gemmBlocks = (NN + 127) / 128;   // 391

    const float* xs[LL]   = { x, buf0, buf1 };
    float*       outs[LL] = { buf0, buf1, out };

    // fork: weight prep + layer-0 root GEMM run on s2 under the CSR build
    cudaEventRecord(R.evA[0], 0);
    cudaStreamWaitEvent(R.s2, R.evA[0], 0);
    wprep_kernel<<<(LL * 256 * DD + T - 1) / T, T, 0, R.s2>>>(Wrel, Wroot);
    gemm_half_kernel<<<gemmBlocks, T, 2 * BUFB, R.s2>>>(
        x, 0, 64, bias, outs[0], 0);                 // out0 = x@Wroot0 + b0
    cudaEventRecord(R.evB[0], R.s2);

    // main: CSR build
    zero_counts_kernel<<<gbN, T>>>();
    detect_kernel<<<16, 256>>>((const unsigned int*)edges);
    convert_hist_kernel<<<gbE, T>>>(edges);
    scan_red_kernel<<<NB, 256>>>();
    scan_mid_kernel<<<1, 256>>>();
    scan_final_kernel<<<NB, 256>>>();
    fill_kernel<<<gbE, T>>>();

    for (int l = 0; l < LL; l++) {
        if (l > 0) {
            // fork root GEMM of layer l (x_l ready after rel GEMM of l-1)
            cudaEventRecord(R.evA[l], 0);
            cudaStreamWaitEvent(R.s2, R.evA[l], 0);
            gemm_half_kernel<<<gemmBlocks, T, 2 * BUFB, R.s2>>>(
                xs[l], l, 64, bias + (size_t)l * DD, outs[l], 0);
            cudaEventRecord(R.evB[l], R.s2);
        }
        agg_kernel<<<aggBlocks, T>>>(xs[l]);         // concurrent with root GEMM
        cudaStreamWaitEvent(0, R.evB[l], 0);         // join
        gemm_half_kernel<<<gemmBlocks, T, 2 * BUFB>>>(
            aggp, l, 0, nullptr, outs[l], 1);        // out_l += agg@Wrel_l
    }
}

// round 8
// speedup vs baseline: 1.3125x; 1.2788x over previous
#include <cuda_runtime.h>
#include <cuda_bf16.h>
#include <cstdint>

#define NN 50000
#define EE 800000
#define DD 128
#define LL 3
#define NB 196                        // scan blocks: ceil(50000/256)

// ---------------- device scratch ----------------
__device__ float g_buf0[NN * DD];
__device__ float g_buf1[NN * DD];
__device__ float g_agg [NN * DD];
__device__ int   g_rowptr[NN + 1];
__device__ int   g_counts[NN];
__device__ int   g_bsum[NB];
__device__ int   g_srcs  [EE];
__device__ int   g_src_in[EE];
__device__ int   g_dst_in[EE];
__device__ int   g_is32;
// transposed bf16 weights: [layer][n=128][k=256] (k<128 -> Wrel, else Wroot)
__device__ unsigned short g_Bth[LL * DD * 2 * DD];
__device__ unsigned short g_Btl[LL * DD * 2 * DD];

// ---------------- CSR build ----------------
// zero counts + int32/int64 detection in one kernel.
// Detection: sample first 16384 odd 32-bit words. int64 edges -> all high
// halves zero; int32 -> 16k uniform indices, all-zero impossible.
__global__ void zero_detect_kernel(const unsigned int* __restrict__ w) {
    int i = blockIdx.x * blockDim.x + threadIdx.x;
    if (i == 0) g_is32 = 0;
    if (i < NN) g_counts[i] = 0;
    if (i < 4096) {
        unsigned int acc = 0;
        #pragma unroll
        for (int j = 0; j < 4; j++) acc |= w[2 * (i * 4 + j) + 1];
        if (acc) g_is32 = 1;
    }
}

__global__ void convert_hist_kernel(const void* __restrict__ edges) {
    int e = blockIdx.x * blockDim.x + threadIdx.x;
    if (e >= EE) return;
    int s, d;
    if (g_is32) {
        const int* p = (const int*)edges;
        s = p[e]; d = p[EE + e];
    } else {
        const long long* p = (const long long*)edges;
        s = (int)p[e]; d = (int)p[EE + e];
    }
    g_src_in[e] = s;
    g_dst_in[e] = d;
    atomicAdd(&g_counts[d], 1);
}

__global__ void scan_red_kernel() {
    __shared__ int s[256];
    int b = blockIdx.x, t = threadIdx.x;
    int i = b * 256 + t;
    s[t] = (i < NN) ? g_counts[i] : 0;
    __syncthreads();
    #pragma unroll
    for (int o = 128; o > 0; o >>= 1) {
        if (t < o) s[t] += s[t + o];
        __syncthreads();
    }
    if (t == 0) g_bsum[b] = s[0];
}

__global__ void scan_mid_kernel() {
    __shared__ int s[256];
    int t = threadIdx.x;
    int v = (t < NB) ? g_bsum[t] : 0;
    s[t] = v;
    __syncthreads();
    #pragma unroll
    for (int o = 1; o < 256; o <<= 1) {
        int u = (t >= o) ? s[t - o] : 0;
        __syncthreads();
        s[t] += u;
        __syncthreads();
    }
    if (t < NB) g_bsum[t] = s[t] - v;
    if (t == 255) g_rowptr[NN] = s[255];
}

__global__ void scan_final_kernel() {
    __shared__ int s[256];
    int b = blockIdx.x, t = threadIdx.x;
    int i = b * 256 + t;
    int v = (i < NN) ? g_counts[i] : 0;
    s[t] = v;
    __syncthreads();
    #pragma unroll
    for (int o = 1; o < 256; o <<= 1) {
        int u = (t >= o) ? s[t - o] : 0;
        __syncthreads();
        s[t] += u;
        __syncthreads();
    }
    if (i < NN) {
        g_rowptr[i] = g_bsum[b] + s[t] - v;
        g_counts[i] = 0;
    }
}

__global__ void fill_kernel() {
    int e = blockIdx.x * blockDim.x + threadIdx.x;
    if (e >= EE) return;
    int d = g_dst_in[e];
    int pos = g_rowptr[d] + atomicAdd(&g_counts[d], 1);
    g_srcs[pos] = g_src_in[e];
}

// ---------------- weight prep ----------------
__global__ void wprep_kernel(const float* __restrict__ Wrel,
                             const float* __restrict__ Wroot) {
    int idx = blockIdx.x * blockDim.x + threadIdx.x;
    if (idx >= LL * 256 * DD) return;
    int l = idx / (256 * DD);
    int r = idx - l * 256 * DD;
    int k = r / DD;
    int n = r - k * DD;
    float w = (k < DD) ? Wrel[(size_t)l * DD * DD + k * DD + n]
                       : Wroot[(size_t)l * DD * DD + (k - DD) * DD + n];
    __nv_bfloat16 hi = __float2bfloat16(w);
    float lo = w - __bfloat162float(hi);
    __nv_bfloat16 lob = __float2bfloat16(lo);
    size_t o = (size_t)l * DD * 256 + (size_t)n * 256 + k;
    g_Bth[o] = *(unsigned short*)&hi;
    g_Btl[o] = *(unsigned short*)&lob;
}

// ---------------- aggregation: one warp per destination node, unroll x4 -----
__global__ void agg_kernel(const float* __restrict__ x) {
    int gw   = (blockIdx.x * blockDim.x + threadIdx.x) >> 5;
    int lane = threadIdx.x & 31;
    if (gw >= NN) return;
    int beg = g_rowptr[gw], end = g_rowptr[gw + 1];
    float4 acc = make_float4(0.f, 0.f, 0.f, 0.f);
    const float* xb = x + lane * 4;
    int e = beg;
    for (; e + 3 < end; e += 4) {
        int s0 = g_srcs[e], s1 = g_srcs[e+1], s2 = g_srcs[e+2], s3 = g_srcs[e+3];
        float4 v0 = *(const float4*)(xb + (size_t)s0 * DD);
        float4 v1 = *(const float4*)(xb + (size_t)s1 * DD);
        float4 v2 = *(const float4*)(xb + (size_t)s2 * DD);
        float4 v3 = *(const float4*)(xb + (size_t)s3 * DD);
        acc.x += (v0.x + v1.x) + (v2.x + v3.x);
        acc.y += (v0.y + v1.y) + (v2.y + v3.y);
        acc.z += (v0.z + v1.z) + (v2.z + v3.z);
        acc.w += (v0.w + v1.w) + (v2.w + v3.w);
    }
    for (; e < end; e++) {
        float4 v = *(const float4*)(xb + (size_t)g_srcs[e] * DD);
        acc.x += v.x; acc.y += v.y; acc.z += v.z; acc.w += v.w;
    }
    *(float4*)(g_agg + (size_t)gw * DD + lane * 4) = acc;
}

// ---------------- fused tensor-core GEMM via mma.sync (HMMA) -----------------
// out[m][n] = sum_k A[m][k] W[k][n] + bias[n];  A = [agg | x]  (virtual K=256).
// Split bf16: acc += Ahi*Bhi + Ahi*Blo + Alo*Bhi.
// BM=128, BN=128, BK=32, 256 threads = 8 warps, warp tile 64x32.
// smem rows padded to 40 bf16 (80B) -> conflict-free fragment loads.

#define BK 32
#define ROWB 80
#define BUFB 40960                    // 4 planes * 128 rows * 80B
#define OFF_AH 0
#define OFF_AL 10240
#define OFF_BH 20480
#define OFF_BL 30720

__device__ __forceinline__ void mma16816(float* c, const uint32_t* a, const uint32_t* b) {
    asm volatile(
        "mma.sync.aligned.m16n8k16.row.col.f32.bf16.bf16.f32 "
        "{%0,%1,%2,%3}, {%4,%5,%6,%7}, {%8,%9}, {%0,%1,%2,%3};"
        : "+f"(c[0]), "+f"(c[1]), "+f"(c[2]), "+f"(c[3])
        : "r"(a[0]), "r"(a[1]), "r"(a[2]), "r"(a[3]), "r"(b[0]), "r"(b[1]));
}

__device__ __forceinline__ uint32_t pack_bf2f(float a, float b) {
    __nv_bfloat16 ha = __float2bfloat16(a), hb = __float2bfloat16(b);
    uint16_t ua = *(uint16_t*)&ha, ub = *(uint16_t*)&hb;
    return (uint32_t)ua | ((uint32_t)ub << 16);
}

__global__ void __launch_bounds__(256) gemm_mma_kernel(
    const float* __restrict__ xin,
    int layer,
    const float* __restrict__ bias,
    float* __restrict__ out)
{
    extern __shared__ char smem[];
    int tid  = threadIdx.x;
    int wid  = tid >> 5;
    int lane = tid & 31;
    int g    = lane >> 2;
    int t    = lane & 3;
    int row0 = blockIdx.x * 128;
    int m0w  = (wid >> 2) * 64;
    int n0w  = (wid & 3) * 32;

    const uint32_t* Bth = (const uint32_t*)(g_Bth + (size_t)layer * DD * 256);
    const uint32_t* Btl = (const uint32_t*)(g_Btl + (size_t)layer * DD * 256);

    float acc[4][4][4];
    #pragma unroll
    for (int i = 0; i < 4; i++)
        #pragma unroll
        for (int j = 0; j < 4; j++)
            #pragma unroll
            for (int q = 0; q < 4; q++) acc[i][j][q] = 0.f;

    float4   av[4];
    uint32_t bhv[8], blv[8];

    auto load_regs = [&](int c) {
        int kv0 = c * BK;
        const float* src = (kv0 < DD) ? g_agg : xin;
        int kc = kv0 & 127;
        #pragma unroll
        for (int j = 0; j < 4; j++) {
            int p = j * 256 + tid;
            int m = p >> 3;
            int kq = p & 7;
            int grow = row0 + m;
            av[j] = make_float4(0.f, 0.f, 0.f, 0.f);
            if (grow < NN)
                av[j] = *(const float4*)(src + (size_t)grow * DD + kc + 4 * kq);
        }
        #pragma unroll
        for (int j = 0; j < 8; j++) {
            int p = j * 256 + tid;
            int n = p >> 4;
            int kp = p & 15;
            int ui = n * 128 + c * 16 + kp;
            bhv[j] = Bth[ui];
            blv[j] = Btl[ui];
        }
    };

    auto store_smem = [&](int buf) {
        char* base = smem + buf * BUFB;
        #pragma unroll
        for (int j = 0; j < 4; j++) {
            int p = j * 256 + tid;
            int m = p >> 3;
            int kq = p & 7;
            float4 v = av[j];
            float lx = v.x - __bfloat162float(__float2bfloat16(v.x));
            float ly = v.y - __bfloat162float(__float2bfloat16(v.y));
            float lz = v.z - __bfloat162float(__float2bfloat16(v.z));
            float lw = v.w - __bfloat162float(__float2bfloat16(v.w));
            uint32_t off = (uint32_t)m * ROWB + 8 * kq;
            *(uint32_t*)(base + OFF_AH + off)     = pack_bf2f(v.x, v.y);
            *(uint32_t*)(base + OFF_AH + off + 4) = pack_bf2f(v.z, v.w);
            *(uint32_t*)(base + OFF_AL + off)     = pack_bf2f(lx, ly);
            *(uint32_t*)(base + OFF_AL + off + 4) = pack_bf2f(lz, lw);
        }
        #pragma unroll
        for (int j = 0; j < 8; j++) {
            int p = j * 256 + tid;
            int n = p >> 4;
            int kp = p & 15;
            uint32_t off = (uint32_t)n * ROWB + 4 * kp;
            *(uint32_t*)(base + OFF_BH + off) = bhv[j];
            *(uint32_t*)(base + OFF_BL + off) = blv[j];
        }
    };

    load_regs(0);
    store_smem(0);
    __syncthreads();

    #pragma unroll 1
    for (int c = 0; c < 8; c++) {
        if (c < 7) load_regs(c + 1);

        const char* base = smem + (c & 1) * BUFB;
        #pragma unroll
        for (int s = 0; s < 2; s++) {
            uint32_t ah[4][4], al[4][4], bh[4][2], bl[4][2];
            #pragma unroll
            for (int mt = 0; mt < 4; mt++) {
                uint32_t r0 = (uint32_t)(m0w + mt * 16 + g) * ROWB + s * 32 + 4 * t;
                uint32_t r1 = r0 + 8 * ROWB;
                ah[mt][0] = *(const uint32_t*)(base + OFF_AH + r0);
                ah[mt][1] = *(const uint32_t*)(base + OFF_AH + r1);
                ah[mt][2] = *(const uint32_t*)(base + OFF_AH + r0 + 16);
                ah[mt][3] = *(const uint32_t*)(base + OFF_AH + r1 + 16);
                al[mt][0] = *(const uint32_t*)(base + OFF_AL + r0);
                al[mt][1] = *(const uint32_t*)(base + OFF_AL + r1);
                al[mt][2] = *(const uint32_t*)(base + OFF_AL + r0 + 16);
                al[mt][3] = *(const uint32_t*)(base + OFF_AL + r1 + 16);
            }
            #pragma unroll
            for (int nt = 0; nt < 4; nt++) {
                uint32_t rb = (uint32_t)(n0w + nt * 8 + g) * ROWB + s * 32 + 4 * t;
                bh[nt][0] = *(const uint32_t*)(base + OFF_BH + rb);
                bh[nt][1] = *(const uint32_t*)(base + OFF_BH + rb + 16);
                bl[nt][0] = *(const uint32_t*)(base + OFF_BL + rb);
                bl[nt][1] = *(const uint32_t*)(base + OFF_BL + rb + 16);
            }
            #pragma unroll
            for (int mt = 0; mt < 4; mt++)
                #pragma unroll
                for (int nt = 0; nt < 4; nt++) {
                    mma16816(acc[mt][nt], ah[mt], bh[nt]);
                    mma16816(acc[mt][nt], ah[mt], bl[nt]);
                    mma16816(acc[mt][nt], al[mt], bh[nt]);
                }
        }
        if (c < 7) {
            store_smem((c + 1) & 1);
            __syncthreads();
        }
    }

    #pragma unroll
    for (int nt = 0; nt < 4; nt++) {
        int col = n0w + nt * 8 + 2 * t;
        float b0 = bias[col], b1 = bias[col + 1];
        #pragma unroll
        for (int mt = 0; mt < 4; mt++) {
            int r = row0 + m0w + mt * 16 + g;
            if (r < NN) {
                float2 o0 = make_float2(acc[mt][nt][0] + b0, acc[mt][nt][1] + b1);
                *(float2*)(out + (size_t)r * DD + col) = o0;
            }
            if (r + 8 < NN) {
                float2 o1 = make_float2(acc[mt][nt][2] + b0, acc[mt][nt][3] + b1);
                *(float2*)(out + (size_t)(r + 8) * DD + col) = o1;
            }
        }
    }
}

// ---------------- launch ----------------
extern "C" void kernel_launch(void* const* d_in, const int* in_sizes, int n_in,
                              void* d_out, int out_size) {
    const float* x     = (const float*)d_in[0];
    const void*  edges = d_in[1];
    const float* Wrel  = (const float*)d_in[2];
    const float* Wroot = (const float*)d_in[3];
    const float* bias  = (const float*)d_in[4];
    float*       out   = (float*)d_out;

    float *buf0, *buf1;
    cudaGetSymbolAddress((void**)&buf0, g_buf0);
    cudaGetSymbolAddress((void**)&buf1, g_buf1);

    cudaFuncSetAttribute(gemm_mma_kernel,
                         cudaFuncAttributeMaxDynamicSharedMemorySize, 2 * BUFB);

    const int T = 256;
    int gbN = (NN + T - 1) / T;
    int gbE = (EE + T - 1) / T;

    zero_detect_kernel<<<gbN, T>>>((const unsigned int*)edges);
    convert_hist_kernel<<<gbE, T>>>(edges);
    scan_red_kernel<<<NB, 256>>>();
    scan_mid_kernel<<<1, 256>>>();
    scan_final_kernel<<<NB, 256>>>();
    fill_kernel<<<gbE, T>>>();
    wprep_kernel<<<(LL * 256 * DD + T - 1) / T, T>>>(Wrel, Wroot);

    int aggBlocks  = (NN * 32 + T - 1) / T;
    int gemmBlocks = (NN + 127) / 128;   // 391

    const float* cur = x;
    float* outs[LL] = { buf0, buf1, out };
    for (int l = 0; l < LL; l++) {
        agg_kernel<<<aggBlocks, T>>>(cur);
        gemm_mma_kernel<<<gemmBlocks, T, 2 * BUFB>>>(cur, l, bias + (size_t)l * DD,
                                                     outs[l]);
        cur = outs[l];
    }
}

// round 9
// speedup vs baseline: 1.3838x; 1.0543x over previous
#include <cuda_runtime.h>
#include <cuda_bf16.h>
#include <cstdint>

#define NN 50000
#define EE 800000
#define DD 128
#define LL 3
#define NB 196                        // scan blocks: ceil(50000/256)

// ---------------- device scratch ----------------
__device__ float g_buf0[NN * DD];
__device__ float g_buf1[NN * DD];
__device__ float g_agg [NN * DD];
__device__ int   g_rowptr[NN + 1];
__device__ int   g_counts[NN];
__device__ int   g_bsum[NB];
__device__ int   g_srcs  [EE];
__device__ int   g_src_in[EE];
__device__ int   g_dst_in[EE];
__device__ int   g_is32;
// transposed bf16 weights: [layer][n=128][k=256] (k<128 -> Wrel, else Wroot)
__device__ unsigned short g_Bth[LL * DD * 2 * DD];
__device__ unsigned short g_Btl[LL * DD * 2 * DD];

// ---------------- CSR build ----------------
__global__ void zero_detect_kernel(const unsigned int* __restrict__ w) {
    int i = blockIdx.x * blockDim.x + threadIdx.x;
    if (i == 0) g_is32 = 0;
    if (i < NN) g_counts[i] = 0;
    if (i < 4096) {
        unsigned int acc = 0;
        #pragma unroll
        for (int j = 0; j < 4; j++) acc |= w[2 * (i * 4 + j) + 1];
        if (acc) g_is32 = 1;
    }
}

__global__ void convert_hist_kernel(const void* __restrict__ edges) {
    int e = blockIdx.x * blockDim.x + threadIdx.x;
    if (e >= EE) return;
    int s, d;
    if (g_is32) {
        const int* p = (const int*)edges;
        s = p[e]; d = p[EE + e];
    } else {
        const long long* p = (const long long*)edges;
        s = (int)p[e]; d = (int)p[EE + e];
    }
    g_src_in[e] = s;
    g_dst_in[e] = d;
    atomicAdd(&g_counts[d], 1);
}

__global__ void scan_red_kernel() {
    __shared__ int s[256];
    int b = blockIdx.x, t = threadIdx.x;
    int i = b * 256 + t;
    s[t] = (i < NN) ? g_counts[i] : 0;
    __syncthreads();
    #pragma unroll
    for (int o = 128; o > 0; o >>= 1) {
        if (t < o) s[t] += s[t + o];
        __syncthreads();
    }
    if (t == 0) g_bsum[b] = s[0];
}

__global__ void scan_mid_kernel() {
    __shared__ int s[256];
    int t = threadIdx.x;
    int v = (t < NB) ? g_bsum[t] : 0;
    s[t] = v;
    __syncthreads();
    #pragma unroll
    for (int o = 1; o < 256; o <<= 1) {
        int u = (t >= o) ? s[t - o] : 0;
        __syncthreads();
        s[t] += u;
        __syncthreads();
    }
    if (t < NB) g_bsum[t] = s[t] - v;
    if (t == 255) g_rowptr[NN] = s[255];
}

__global__ void scan_final_kernel() {
    __shared__ int s[256];
    int b = blockIdx.x, t = threadIdx.x;
    int i = b * 256 + t;
    int v = (i < NN) ? g_counts[i] : 0;
    s[t] = v;
    __syncthreads();
    #pragma unroll
    for (int o = 1; o < 256; o <<= 1) {
        int u = (t >= o) ? s[t - o] : 0;
        __syncthreads();
        s[t] += u;
        __syncthreads();
    }
    if (i < NN) {
        g_rowptr[i] = g_bsum[b] + s[t] - v;
        g_counts[i] = 0;
    }
}

__global__ void fill_kernel() {
    int e = blockIdx.x * blockDim.x + threadIdx.x;
    if (e >= EE) return;
    int d = g_dst_in[e];
    int pos = g_rowptr[d] + atomicAdd(&g_counts[d], 1);
    g_srcs[pos] = g_src_in[e];
}

// ---------------- weight prep ----------------
__global__ void wprep_kernel(const float* __restrict__ Wrel,
                             const float* __restrict__ Wroot) {
    int idx = blockIdx.x * blockDim.x + threadIdx.x;
    if (idx >= LL * 256 * DD) return;
    int l = idx / (256 * DD);
    int r = idx - l * 256 * DD;
    int k = r / DD;
    int n = r - k * DD;
    float w = (k < DD) ? Wrel[(size_t)l * DD * DD + k * DD + n]
                       : Wroot[(size_t)l * DD * DD + (k - DD) * DD + n];
    __nv_bfloat16 hi = __float2bfloat16(w);
    float lo = w - __bfloat162float(hi);
    __nv_bfloat16 lob = __float2bfloat16(lo);
    size_t o = (size_t)l * DD * 256 + (size_t)n * 256 + k;
    g_Bth[o] = *(unsigned short*)&hi;
    g_Btl[o] = *(unsigned short*)&lob;
}

// ---------------- aggregation: one warp per destination node ----------------
__global__ void agg_kernel(const float* __restrict__ x) {
    int gw   = (blockIdx.x * blockDim.x + threadIdx.x) >> 5;
    int lane = threadIdx.x & 31;
    if (gw >= NN) return;
    int beg = g_rowptr[gw], end = g_rowptr[gw + 1];
    float4 acc = make_float4(0.f, 0.f, 0.f, 0.f);
    const float* xb = x + lane * 4;
    int e = beg;
    for (; e + 3 < end; e += 4) {
        int s0 = g_srcs[e], s1 = g_srcs[e+1], s2 = g_srcs[e+2], s3 = g_srcs[e+3];
        float4 v0 = *(const float4*)(xb + (size_t)s0 * DD);
        float4 v1 = *(const float4*)(xb + (size_t)s1 * DD);
        float4 v2 = *(const float4*)(xb + (size_t)s2 * DD);
        float4 v3 = *(const float4*)(xb + (size_t)s3 * DD);
        acc.x += (v0.x + v1.x) + (v2.x + v3.x);
        acc.y += (v0.y + v1.y) + (v2.y + v3.y);
        acc.z += (v0.z + v1.z) + (v2.z + v3.z);
        acc.w += (v0.w + v1.w) + (v2.w + v3.w);
    }
    for (; e < end; e++) {
        float4 v = *(const float4*)(xb + (size_t)g_srcs[e] * DD);
        acc.x += v.x; acc.y += v.y; acc.z += v.z; acc.w += v.w;
    }
    *(float4*)(g_agg + (size_t)gw * DD + lane * 4) = acc;
}

// ---------------- fused tensor-core GEMM via mma.sync + ldmatrix -------------
// out[m][n] = sum_k A[m][k] W[k][n] + bias[n];  A = [agg | x]  (virtual K=256).
// Split bf16: acc += Ahi*Bhi + Ahi*Blo + Alo*Bhi.
// BM=128, BN=128, BK=32, 256 threads = 8 warps, warp tile 64x32.
// ROWB=80 padding: LDSM rows stride 80B -> addr/4 stride 20 -> 8 rows of each
// 8x8 matrix hit banks {0,20,8,28,16,4,24,12} -> conflict-free.

#define BK 32
#define ROWB 80
#define BUFB 40960                    // 4 planes * 128 rows * 80B
#define OFF_AH 0
#define OFF_AL 10240
#define OFF_BH 20480
#define OFF_BL 30720

__device__ __forceinline__ uint32_t smem_u32(const void* p) {
    uint32_t a;
    asm("{ .reg .u64 t; cvta.to.shared.u64 t, %1; cvt.u32.u64 %0, t; }" : "=r"(a) : "l"(p));
    return a;
}

#define LDSM4(r, a)                                                              \
    asm volatile("ldmatrix.sync.aligned.m8n8.x4.shared.b16 {%0,%1,%2,%3}, [%4];" \
        : "=r"((r)[0]), "=r"((r)[1]), "=r"((r)[2]), "=r"((r)[3]) : "r"(a))

__device__ __forceinline__ void mma16816(float* c, const uint32_t* a, const uint32_t* b) {
    asm volatile(
        "mma.sync.aligned.m16n8k16.row.col.f32.bf16.bf16.f32 "
        "{%0,%1,%2,%3}, {%4,%5,%6,%7}, {%8,%9}, {%0,%1,%2,%3};"
        : "+f"(c[0]), "+f"(c[1]), "+f"(c[2]), "+f"(c[3])
        : "r"(a[0]), "r"(a[1]), "r"(a[2]), "r"(a[3]), "r"(b[0]), "r"(b[1]));
}

__device__ __forceinline__ uint32_t pack_bf2f(float a, float b) {
    __nv_bfloat16 ha = __float2bfloat16(a), hb = __float2bfloat16(b);
    uint16_t ua = *(uint16_t*)&ha, ub = *(uint16_t*)&hb;
    return (uint32_t)ua | ((uint32_t)ub << 16);
}

__global__ void __launch_bounds__(256) gemm_mma_kernel(
    const float* __restrict__ xin,
    int layer,
    const float* __restrict__ bias,
    float* __restrict__ out)
{
    extern __shared__ char smem[];
    int tid  = threadIdx.x;
    int wid  = tid >> 5;
    int lane = tid & 31;
    int g    = lane >> 2;
    int t    = lane & 3;
    int row0 = blockIdx.x * 128;
    int m0w  = (wid >> 2) * 64;
    int n0w  = (wid & 3) * 32;

    uint32_t sb = smem_u32(smem);

    // LDSM address components (constant per thread)
    // A (16x16 tile): mats = {rows0-7 klo, rows8-15 klo, rows0-7 khi, rows8-15 khi}
    uint32_t aoff_c = (uint32_t)(m0w + (lane & 15)) * ROWB + ((lane >> 4) << 4);
    // B (two n8 x k16 tiles): mats = {p0 klo, p0 khi, p1 klo, p1 khi}
    uint32_t boff_c = (uint32_t)(n0w + ((lane >> 4) << 3) + (lane & 7)) * ROWB
                    + (((lane >> 3) & 1) << 4);

    const uint32_t* Bth = (const uint32_t*)(g_Bth + (size_t)layer * DD * 256);
    const uint32_t* Btl = (const uint32_t*)(g_Btl + (size_t)layer * DD * 256);

    float acc[4][4][4];
    #pragma unroll
    for (int i = 0; i < 4; i++)
        #pragma unroll
        for (int j = 0; j < 4; j++)
            #pragma unroll
            for (int q = 0; q < 4; q++) acc[i][j][q] = 0.f;

    float4   av[4];
    uint32_t bhv[8], blv[8];

    auto load_regs = [&](int c) {
        int kv0 = c * BK;
        const float* src = (kv0 < DD) ? g_agg : xin;
        int kc = kv0 & 127;
        #pragma unroll
        for (int j = 0; j < 4; j++) {
            int p = j * 256 + tid;
            int m = p >> 3;
            int kq = p & 7;
            int grow = row0 + m;
            av[j] = make_float4(0.f, 0.f, 0.f, 0.f);
            if (grow < NN)
                av[j] = *(const float4*)(src + (size_t)grow * DD + kc + 4 * kq);
        }
        #pragma unroll
        for (int j = 0; j < 8; j++) {
            int p = j * 256 + tid;
            int n = p >> 4;
            int kp = p & 15;
            int ui = n * 128 + c * 16 + kp;
            bhv[j] = Bth[ui];
            blv[j] = Btl[ui];
        }
    };

    auto store_smem = [&](int buf) {
        char* base = smem + buf * BUFB;
        #pragma unroll
        for (int j = 0; j < 4; j++) {
            int p = j * 256 + tid;
            int m = p >> 3;
            int kq = p & 7;
            float4 v = av[j];
            float lx = v.x - __bfloat162float(__float2bfloat16(v.x));
            float ly = v.y - __bfloat162float(__float2bfloat16(v.y));
            float lz = v.z - __bfloat162float(__float2bfloat16(v.z));
            float lw = v.w - __bfloat162float(__float2bfloat16(v.w));
            uint32_t off = (uint32_t)m * ROWB + 8 * kq;
            *(uint32_t*)(base + OFF_AH + off)     = pack_bf2f(v.x, v.y);
            *(uint32_t*)(base + OFF_AH + off + 4) = pack_bf2f(v.z, v.w);
            *(uint32_t*)(base + OFF_AL + off)     = pack_bf2f(lx, ly);
            *(uint32_t*)(base + OFF_AL + off + 4) = pack_bf2f(lz, lw);
        }
        #pragma unroll
        for (int j = 0; j < 8; j++) {
            int p = j * 256 + tid;
            int n = p >> 4;
            int kp = p & 15;
            uint32_t off = (uint32_t)n * ROWB + 4 * kp;
            *(uint32_t*)(base + OFF_BH + off) = bhv[j];
            *(uint32_t*)(base + OFF_BL + off) = blv[j];
        }
    };

    load_regs(0);
    store_smem(0);
    __syncthreads();

    #pragma unroll 1
    for (int c = 0; c < 8; c++) {
        if (c < 7) load_regs(c + 1);

        uint32_t bu = sb + (c & 1) * BUFB;
        #pragma unroll
        for (int s = 0; s < 2; s++) {
            uint32_t ks = s * 32;
            uint32_t ahq[4][4], alq[4][4], bhq[2][4], blq[2][4];
            #pragma unroll
            for (int mt = 0; mt < 4; mt++) {
                uint32_t adr = bu + OFF_AH + aoff_c + mt * (16 * ROWB) + ks;
                LDSM4(ahq[mt], adr);
                LDSM4(alq[mt], adr + (OFF_AL - OFF_AH));
            }
            #pragma unroll
            for (int p = 0; p < 2; p++) {
                uint32_t bdr = bu + OFF_BH + boff_c + p * (16 * ROWB) + ks;
                LDSM4(bhq[p], bdr);
                LDSM4(blq[p], bdr + (OFF_BL - OFF_BH));
            }
            #pragma unroll
            for (int mt = 0; mt < 4; mt++)
                #pragma unroll
                for (int p = 0; p < 2; p++) {
                    mma16816(acc[mt][2*p],   ahq[mt], &bhq[p][0]);
                    mma16816(acc[mt][2*p],   ahq[mt], &blq[p][0]);
                    mma16816(acc[mt][2*p],   alq[mt], &bhq[p][0]);
                    mma16816(acc[mt][2*p+1], ahq[mt], &bhq[p][2]);
                    mma16816(acc[mt][2*p+1], ahq[mt], &blq[p][2]);
                    mma16816(acc[mt][2*p+1], alq[mt], &bhq[p][2]);
                }
        }
        if (c < 7) {
            store_smem((c + 1) & 1);
            __syncthreads();
        }
    }

    #pragma unroll
    for (int nt = 0; nt < 4; nt++) {
        int col = n0w + nt * 8 + 2 * t;
        float b0 = bias[col], b1 = bias[col + 1];
        #pragma unroll
        for (int mt = 0; mt < 4; mt++) {
            int r = row0 + m0w + mt * 16 + g;
            if (r < NN) {
                float2 o0 = make_float2(acc[mt][nt][0] + b0, acc[mt][nt][1] + b1);
                *(float2*)(out + (size_t)r * DD + col) = o0;
            }
            if (r + 8 < NN) {
                float2 o1 = make_float2(acc[mt][nt][2] + b0, acc[mt][nt][3] + b1);
                *(float2*)(out + (size_t)(r + 8) * DD + col) = o1;
            }
        }
    }
}

// ---------------- launch ----------------
extern "C" void kernel_launch(void* const* d_in, const int* in_sizes, int n_in,
                              void* d_out, int out_size) {
    const float* x     = (const float*)d_in[0];
    const void*  edges = d_in[1];
    const float* Wrel  = (const float*)d_in[2];
    const float* Wroot = (const float*)d_in[3];
    const float* bias  = (const float*)d_in[4];
    float*       out   = (float*)d_out;

    float *buf0, *buf1;
    cudaGetSymbolAddress((void**)&buf0, g_buf0);
    cudaGetSymbolAddress((void**)&buf1, g_buf1);

    cudaFuncSetAttribute(gemm_mma_kernel,
                         cudaFuncAttributeMaxDynamicSharedMemorySize, 2 * BUFB);

    const int T = 256;
    int gbN = (NN + T - 1) / T;
    int gbE = (EE + T - 1) / T;

    zero_detect_kernel<<<gbN, T>>>((const unsigned int*)edges);
    convert_hist_kernel<<<gbE, T>>>(edges);
    scan_red_kernel<<<NB, 256>>>();
    scan_mid_kernel<<<1, 256>>>();
    scan_final_kernel<<<NB, 256>>>();
    fill_kernel<<<gbE, T>>>();
    wprep_kernel<<<(LL * 256 * DD + T - 1) / T, T>>>(Wrel, Wroot);

    int aggBlocks  = (NN * 32 + T - 1) / T;
    int gemmBlocks = (NN + 127) / 128;   // 391

    const float* cur = x;
    float* outs[LL] = { buf0, buf1, out };
    for (int l = 0; l < LL; l++) {
        agg_kernel<<<aggBlocks, T>>>(cur);
        gemm_mma_kernel<<<gemmBlocks, T, 2 * BUFB>>>(cur, l, bias + (size_t)l * DD,
                                                     outs[l]);
        cur = outs[l];
    }
}

// round 10
// speedup vs baseline: 1.3842x; 1.0003x over previous
#include <cuda_runtime.h>
#include <cuda_bf16.h>
#include <cstdint>

#define NN 50000
#define EE 800000
#define DD 128
#define LL 3
#define NB 196                        // scan blocks: ceil(50000/256)
#define WPN (LL * 256 * DD)           // 98304 weight elements

// ---------------- device scratch ----------------
__device__ float g_buf0[NN * DD];
__device__ float g_buf1[NN * DD];
__device__ float g_agg [NN * DD];
__device__ int   g_rowptr[NN + 1];
__device__ int   g_counts[NN];
__device__ int   g_bsum[NB];
__device__ int   g_boff[NB];
__device__ int   g_srcs  [EE];
__device__ int   g_src_in[EE];
__device__ int   g_dst_in[EE];
__device__ int   g_is32;
__device__ int   g_arrive;
__device__ volatile int g_release;
// transposed bf16 weights: [layer][n=128][k=256] (k<128 -> Wrel, else Wroot)
__device__ unsigned short g_Bth[LL * DD * 2 * DD];
__device__ unsigned short g_Btl[LL * DD * 2 * DD];

// ---------------- init: zero counts + dtype detect + weight prep -------------
// grid: 384 blocks x 256 (exactly WPN threads)
__global__ void init_kernel(const unsigned int* __restrict__ w,
                            const float* __restrict__ Wrel,
                            const float* __restrict__ Wroot) {
    int i = blockIdx.x * blockDim.x + threadIdx.x;
    if (i == 0) { g_is32 = 0; g_arrive = 0; g_release = 0; }
    if (i < NN) g_counts[i] = 0;
    // dtype detect: sample first 16384 odd 32-bit words; int64 -> all zero
    if (i < 4096) {
        unsigned int acc = 0;
        #pragma unroll
        for (int j = 0; j < 4; j++) acc |= w[2 * (i * 4 + j) + 1];
        if (acc) g_is32 = 1;
    }
    // weight prep (transpose + bf16 hi/lo split)
    if (i < WPN) {
        int l = i / (256 * DD);
        int r = i - l * 256 * DD;
        int k = r / DD;
        int n = r - k * DD;
        float wv = (k < DD) ? Wrel[(size_t)l * DD * DD + k * DD + n]
                            : Wroot[(size_t)l * DD * DD + (k - DD) * DD + n];
        __nv_bfloat16 hi = __float2bfloat16(wv);
        float lo = wv - __bfloat162float(hi);
        __nv_bfloat16 lob = __float2bfloat16(lo);
        size_t o = (size_t)l * DD * 256 + (size_t)n * 256 + k;
        g_Bth[o] = *(unsigned short*)&hi;
        g_Btl[o] = *(unsigned short*)&lob;
    }
}

__global__ void convert_hist_kernel(const void* __restrict__ edges) {
    int e = blockIdx.x * blockDim.x + threadIdx.x;
    if (e >= EE) return;
    int s, d;
    if (g_is32) {
        const int* p = (const int*)edges;
        s = p[e]; d = p[EE + e];
    } else {
        const long long* p = (const long long*)edges;
        s = (int)p[e]; d = (int)p[EE + e];
    }
    g_src_in[e] = s;
    g_dst_in[e] = d;
    atomicAdd(&g_counts[d], 1);
}

// ---------------- single-kernel scan (grid-sync via atomic ticket) -----------
// 196 blocks; all co-resident (tiny resource use), so the spin is safe.
__global__ void scan_kernel() {
    __shared__ int s[256];
    __shared__ int sel;
    int b = blockIdx.x, t = threadIdx.x;
    int i = b * 256 + t;
    int v = (i < NN) ? g_counts[i] : 0;
    s[t] = v;
    __syncthreads();
    #pragma unroll
    for (int o = 1; o < 256; o <<= 1) {
        int u = (t >= o) ? s[t - o] : 0;
        __syncthreads();
        s[t] += u;
        __syncthreads();
    }
    if (t == 255) {
        g_bsum[b] = s[255];
        __threadfence();
        int tk = atomicAdd(&g_arrive, 1);
        sel = (tk == NB - 1);
    }
    __syncthreads();
    if (sel) {
        // last-arriving block: all bsum visible; exclusive-scan them
        __shared__ int m[256];
        int mv = (t < NB) ? g_bsum[t] : 0;
        m[t] = mv;
        __syncthreads();
        #pragma unroll
        for (int o = 1; o < 256; o <<= 1) {
            int u = (t >= o) ? m[t - o] : 0;
            __syncthreads();
            m[t] += u;
            __syncthreads();
        }
        if (t < NB) g_boff[t] = m[t] - mv;
        if (t == 255) g_rowptr[NN] = m[255];
        __threadfence();
        __syncthreads();
        if (t == 0) g_release = 1;
    } else if (t == 0) {
        while (g_release == 0) { }
    }
    __syncthreads();
    __threadfence();
    if (i < NN) {
        g_rowptr[i] = g_boff[b] + s[t] - v;   // exclusive scan
        g_counts[i] = 0;                      // reset cursor for fill
    }
}

__global__ void fill_kernel() {
    int e = blockIdx.x * blockDim.x + threadIdx.x;
    if (e >= EE) return;
    int d = g_dst_in[e];
    int pos = g_rowptr[d] + atomicAdd(&g_counts[d], 1);
    g_srcs[pos] = g_src_in[e];
}

// ---------------- aggregation: one warp per destination node ----------------
__global__ void agg_kernel(const float* __restrict__ x) {
    int gw   = (blockIdx.x * blockDim.x + threadIdx.x) >> 5;
    int lane = threadIdx.x & 31;
    if (gw >= NN) return;
    int beg = g_rowptr[gw], end = g_rowptr[gw + 1];
    float4 acc = make_float4(0.f, 0.f, 0.f, 0.f);
    const float* xb = x + lane * 4;
    int e = beg;
    for (; e + 3 < end; e += 4) {
        int s0 = g_srcs[e], s1 = g_srcs[e+1], s2 = g_srcs[e+2], s3 = g_srcs[e+3];
        float4 v0 = *(const float4*)(xb + (size_t)s0 * DD);
        float4 v1 = *(const float4*)(xb + (size_t)s1 * DD);
        float4 v2 = *(const float4*)(xb + (size_t)s2 * DD);
        float4 v3 = *(const float4*)(xb + (size_t)s3 * DD);
        acc.x += (v0.x + v1.x) + (v2.x + v3.x);
        acc.y += (v0.y + v1.y) + (v2.y + v3.y);
        acc.z += (v0.z + v1.z) + (v2.z + v3.z);
        acc.w += (v0.w + v1.w) + (v2.w + v3.w);
    }
    for (; e < end; e++) {
        float4 v = *(const float4*)(xb + (size_t)g_srcs[e] * DD);
        acc.x += v.x; acc.y += v.y; acc.z += v.z; acc.w += v.w;
    }
    *(float4*)(g_agg + (size_t)gw * DD + lane * 4) = acc;
}

// ---------------- fused tensor-core GEMM via mma.sync + ldmatrix -------------
#define BK 32
#define ROWB 80
#define BUFB 40960
#define OFF_AH 0
#define OFF_AL 10240
#define OFF_BH 20480
#define OFF_BL 30720

__device__ __forceinline__ uint32_t smem_u32(const void* p) {
    uint32_t a;
    asm("{ .reg .u64 t; cvta.to.shared.u64 t, %1; cvt.u32.u64 %0, t; }" : "=r"(a) : "l"(p));
    return a;
}

#define LDSM4(r, a)                                                              \
    asm volatile("ldmatrix.sync.aligned.m8n8.x4.shared.b16 {%0,%1,%2,%3}, [%4];" \
        : "=r"((r)[0]), "=r"((r)[1]), "=r"((r)[2]), "=r"((r)[3]) : "r"(a))

__device__ __forceinline__ void mma16816(float* c, const uint32_t* a, const uint32_t* b) {
    asm volatile(
        "mma.sync.aligned.m16n8k16.row.col.f32.bf16.bf16.f32 "
        "{%0,%1,%2,%3}, {%4,%5,%6,%7}, {%8,%9}, {%0,%1,%2,%3};"
        : "+f"(c[0]), "+f"(c[1]), "+f"(c[2]), "+f"(c[3])
        : "r"(a[0]), "r"(a[1]), "r"(a[2]), "r"(a[3]), "r"(b[0]), "r"(b[1]));
}

__device__ __forceinline__ uint32_t pack_bf2f(float a, float b) {
    __nv_bfloat16 ha = __float2bfloat16(a), hb = __float2bfloat16(b);
    uint16_t ua = *(uint16_t*)&ha, ub = *(uint16_t*)&hb;
    return (uint32_t)ua | ((uint32_t)ub << 16);
}

__global__ void __launch_bounds__(256) gemm_mma_kernel(
    const float* __restrict__ xin,
    int layer,
    const float* __restrict__ bias,
    float* __restrict__ out)
{
    extern __shared__ char smem[];
    int tid  = threadIdx.x;
    int wid  = tid >> 5;
    int lane = tid & 31;
    int g    = lane >> 2;
    int t    = lane & 3;
    int row0 = blockIdx.x * 128;
    int m0w  = (wid >> 2) * 64;
    int n0w  = (wid & 3) * 32;

    uint32_t sb = smem_u32(smem);
    uint32_t aoff_c = (uint32_t)(m0w + (lane & 15)) * ROWB + ((lane >> 4) << 4);
    uint32_t boff_c = (uint32_t)(n0w + ((lane >> 4) << 3) + (lane & 7)) * ROWB
                    + (((lane >> 3) & 1) << 4);

    const uint32_t* Bth = (const uint32_t*)(g_Bth + (size_t)layer * DD * 256);
    const uint32_t* Btl = (const uint32_t*)(g_Btl + (size_t)layer * DD * 256);

    float acc[4][4][4];
    #pragma unroll
    for (int i = 0; i < 4; i++)
        #pragma unroll
        for (int j = 0; j < 4; j++)
            #pragma unroll
            for (int q = 0; q < 4; q++) acc[i][j][q] = 0.f;

    float4   av[4];
    uint32_t bhv[8], blv[8];

    auto load_regs = [&](int c) {
        int kv0 = c * BK;
        const float* src = (kv0 < DD) ? g_agg : xin;
        int kc = kv0 & 127;
        #pragma unroll
        for (int j = 0; j < 4; j++) {
            int p = j * 256 + tid;
            int m = p >> 3;
            int kq = p & 7;
            int grow = row0 + m;
            av[j] = make_float4(0.f, 0.f, 0.f, 0.f);
            if (grow < NN)
                av[j] = *(const float4*)(src + (size_t)grow * DD + kc + 4 * kq);
        }
        #pragma unroll
        for (int j = 0; j < 8; j++) {
            int p = j * 256 + tid;
            int n = p >> 4;
            int kp = p & 15;
            int ui = n * 128 + c * 16 + kp;
            bhv[j] = Bth[ui];
            blv[j] = Btl[ui];
        }
    };

    auto store_smem = [&](int buf) {
        char* base = smem + buf * BUFB;
        #pragma unroll
        for (int j = 0; j < 4; j++) {
            int p = j * 256 + tid;
            int m = p >> 3;
            int kq = p & 7;
            float4 v = av[j];
            float lx = v.x - __bfloat162float(__float2bfloat16(v.x));
            float ly = v.y - __bfloat162float(__float2bfloat16(v.y));
            float lz = v.z - __bfloat162float(__float2bfloat16(v.z));
            float lw = v.w - __bfloat162float(__float2bfloat16(v.w));
            uint32_t off = (uint32_t)m * ROWB + 8 * kq;
            *(uint32_t*)(base + OFF_AH + off)     = pack_bf2f(v.x, v.y);
            *(uint32_t*)(base + OFF_AH + off + 4) = pack_bf2f(v.z, v.w);
            *(uint32_t*)(base + OFF_AL + off)     = pack_bf2f(lx, ly);
            *(uint32_t*)(base + OFF_AL + off + 4) = pack_bf2f(lz, lw);
        }
        #pragma unroll
        for (int j = 0; j < 8; j++) {
            int p = j * 256 + tid;
            int n = p >> 4;
            int kp = p & 15;
            uint32_t off = (uint32_t)n * ROWB + 4 * kp;
            *(uint32_t*)(base + OFF_BH + off) = bhv[j];
            *(uint32_t*)(base + OFF_BL + off) = blv[j];
        }
    };

    load_regs(0);
    store_smem(0);
    __syncthreads();

    #pragma unroll 1
    for (int c = 0; c < 8; c++) {
        if (c < 7) load_regs(c + 1);

        uint32_t bu = sb + (c & 1) * BUFB;
        #pragma unroll
        for (int s = 0; s < 2; s++) {
            uint32_t ks = s * 32;
            uint32_t ahq[4][4], alq[4][4], bhq[2][4], blq[2][4];
            #pragma unroll
            for (int mt = 0; mt < 4; mt++) {
                uint32_t adr = bu + OFF_AH + aoff_c + mt * (16 * ROWB) + ks;
                LDSM4(ahq[mt], adr);
                LDSM4(alq[mt], adr + (OFF_AL - OFF_AH));
            }
            #pragma unroll
            for (int p = 0; p < 2; p++) {
                uint32_t bdr = bu + OFF_BH + boff_c + p * (16 * ROWB) + ks;
                LDSM4(bhq[p], bdr);
                LDSM4(blq[p], bdr + (OFF_BL - OFF_BH));
            }
            #pragma unroll
            for (int mt = 0; mt < 4; mt++)
                #pragma unroll
                for (int p = 0; p < 2; p++) {
                    mma16816(acc[mt][2*p],   ahq[mt], &bhq[p][0]);
                    mma16816(acc[mt][2*p],   ahq[mt], &blq[p][0]);
                    mma16816(acc[mt][2*p],   alq[mt], &bhq[p][0]);
                    mma16816(acc[mt][2*p+1], ahq[mt], &bhq[p][2]);
                    mma16816(acc[mt][2*p+1], ahq[mt], &blq[p][2]);
                    mma16816(acc[mt][2*p+1], alq[mt], &bhq[p][2]);
                }
        }
        if (c < 7) {
            store_smem((c + 1) & 1);
            __syncthreads();
        }
    }

    #pragma unroll
    for (int nt = 0; nt < 4; nt++) {
        int col = n0w + nt * 8 + 2 * t;
        float b0 = bias[col], b1 = bias[col + 1];
        #pragma unroll
        for (int mt = 0; mt < 4; mt++) {
            int r = row0 + m0w + mt * 16 + g;
            if (r < NN) {
                float2 o0 = make_float2(acc[mt][nt][0] + b0, acc[mt][nt][1] + b1);
                *(float2*)(out + (size_t)r * DD + col) = o0;
            }
            if (r + 8 < NN) {
                float2 o1 = make_float2(acc[mt][nt][2] + b0, acc[mt][nt][3] + b1);
                *(float2*)(out + (size_t)(r + 8) * DD + col) = o1;
            }
        }
    }
}

// ---------------- launch ----------------
extern "C" void kernel_launch(void* const* d_in, const int* in_sizes, int n_in,
                              void* d_out, int out_size) {
    const float* x     = (const float*)d_in[0];
    const void*  edges = d_in[1];
    const float* Wrel  = (const float*)d_in[2];
    const float* Wroot = (const float*)d_in[3];
    const float* bias  = (const float*)d_in[4];
    float*       out   = (float*)d_out;

    float *buf0, *buf1;
    cudaGetSymbolAddress((void**)&buf0, g_buf0);
    cudaGetSymbolAddress((void**)&buf1, g_buf1);

    cudaFuncSetAttribute(gemm_mma_kernel,
                         cudaFuncAttributeMaxDynamicSharedMemorySize, 2 * BUFB);

    const int T = 256;
    int gbE = (EE + T - 1) / T;

    init_kernel<<<WPN / T, T>>>((const unsigned int*)edges, Wrel, Wroot);
    convert_hist_kernel<<<gbE, T>>>(edges);
    scan_kernel<<<NB, 256>>>();
    fill_kernel<<<gbE, T>>>();

    int aggBlocks  = (NN * 32 + T - 1) / T;
    int gemmBlocks = (NN + 127) / 128;   // 391

    const float* cur = x;
    float* outs[LL] = { buf0, buf1, out };
    for (int l = 0; l < LL; l++) {
        agg_kernel<<<aggBlocks, T>>>(cur);
        gemm_mma_kernel<<<gemmBlocks, T, 2 * BUFB>>>(cur, l, bias + (size_t)l * DD,
                                                     outs[l]);
        cur = outs[l];
    }
}